// round 14
// baseline (speedup 1.0000x reference)
#include <cuda_runtime.h>
#include <cuda_fp16.h>
#include <cstdint>

// ============================================================================
// RPNHead via Winograd F(2x2,3x3). R14:
//  - GEMM: revert to proven 3-stage single-barrier pipeline (R12, 567us).
//  - FUSED output-transform + head: head CTAs produce their A tiles from g_M
//    (At M A + bias + relu6) directly into smem; g_sh roundtrip eliminated.
// ============================================================================
#define NPOS 131072
#define NTIL 32768
#define OFF_PROBS  3932160
#define OFF_DELTAS 7864320

__device__ __align__(1024) __half g_V [(size_t)16*NTIL*256];   // input transform
__device__ __align__(1024) __half g_wU[(size_t)16*512*256];    // weight transform
__device__ __align__(1024) __half g_M [(size_t)16*NTIL*512];   // GEMM results (fp16)
__device__ __align__(1024) __half g_wh[(size_t)128*512];       // head W [j][c]

__device__ __forceinline__ uint32_t smem_u32(const void* p) {
    uint32_t a;
    asm("{ .reg .u64 t; cvta.to.shared.u64 t, %1; cvt.u32.u64 %0, t; }"
        : "=r"(a) : "l"(p));
    return a;
}

#define CP_ASYNC16(dst, src, sz) \
    asm volatile("cp.async.cg.shared.global [%0], [%1], 16, %2;" \
        :: "r"((uint32_t)(dst)), "l"(src), "r"((int)(sz)) : "memory")
#define CP_COMMIT() asm volatile("cp.async.commit_group;" ::: "memory")
#define CP_WAIT1()  asm volatile("cp.async.wait_group 1;" ::: "memory")
#define CP_WAIT0()  asm volatile("cp.async.wait_group 0;" ::: "memory")

__device__ __forceinline__ void ldm4(uint32_t* f, uint32_t addr) {
    asm volatile("ldmatrix.sync.aligned.m8n8.x4.shared.b16 {%0,%1,%2,%3}, [%4];"
        : "=r"(f[0]), "=r"(f[1]), "=r"(f[2]), "=r"(f[3]) : "r"(addr));
}
__device__ __forceinline__ void mma16816(float* c, const uint32_t* a,
                                         uint32_t b0, uint32_t b1) {
    asm volatile("mma.sync.aligned.m16n8k16.row.col.f32.f16.f16.f32 "
        "{%0,%1,%2,%3}, {%4,%5,%6,%7}, {%8,%9}, {%0,%1,%2,%3};"
        : "+f"(c[0]), "+f"(c[1]), "+f"(c[2]), "+f"(c[3])
        : "r"(a[0]), "r"(a[1]), "r"(a[2]), "r"(a[3]), "r"(b0), "r"(b1));
}

// ============================================================================
// Kernel 1: input transform V = Bt d B, 8 tiles per block, sliding window.
// grid = 4096: b(8) x th(64) x wgrp(8). 128 threads (channel pairs).
// ============================================================================
__global__ void wino_in_kernel(const float* __restrict__ x) {
    const int blk = blockIdx.x;
    const int wgrp = blk & 7;
    const int th = (blk >> 3) & 63;
    const int b = blk >> 9;
    const int c2 = threadIdx.x;
    const int tw0 = wgrp * 8;
    const int h0 = th * 2 - 1;
    const int wbase = tw0 * 2 - 1;

    bool hv[4];
    const float* rowp[4];
    #pragma unroll
    for (int i = 0; i < 4; ++i) {
        const int h = h0 + i;
        hv[i] = (h >= 0) && (h < 128);
        rowp[i] = x + ((size_t)((b * 128 + (hv[i] ? h : 0)) * 128)) * 256 + 2 * c2;
    }

    auto ldcol = [&](int i, int wc) -> float2 {
        if (hv[i] && wc >= 0 && wc < 128)
            return *reinterpret_cast<const float2*>(rowp[i] + (size_t)wc * 256);
        return make_float2(0.0f, 0.0f);
    };

    float2 d[4][4];
    #pragma unroll
    for (int i = 0; i < 4; ++i)
        #pragma unroll
        for (int j = 0; j < 4; ++j)
            d[i][j] = ldcol(i, wbase + j);

    #pragma unroll
    for (int k = 0; k < 8; ++k) {
        const int t = (b * 64 + th) * 64 + (tw0 + k);
        float2 tr[4][4];
        #pragma unroll
        for (int j = 0; j < 4; ++j) {
            tr[0][j] = make_float2(d[0][j].x - d[2][j].x, d[0][j].y - d[2][j].y);
            tr[1][j] = make_float2(d[1][j].x + d[2][j].x, d[1][j].y + d[2][j].y);
            tr[2][j] = make_float2(d[2][j].x - d[1][j].x, d[2][j].y - d[1][j].y);
            tr[3][j] = make_float2(d[1][j].x - d[3][j].x, d[1][j].y - d[3][j].y);
        }
        #pragma unroll
        for (int i = 0; i < 4; ++i) {
            float2 v0 = make_float2(tr[i][0].x - tr[i][2].x, tr[i][0].y - tr[i][2].y);
            float2 v1 = make_float2(tr[i][1].x + tr[i][2].x, tr[i][1].y + tr[i][2].y);
            float2 v2 = make_float2(tr[i][2].x - tr[i][1].x, tr[i][2].y - tr[i][1].y);
            float2 v3 = make_float2(tr[i][1].x - tr[i][3].x, tr[i][1].y - tr[i][3].y);
            *reinterpret_cast<__half2*>(g_V + ((size_t)(i*4+0)*NTIL + t)*256 + 2*c2) = __floats2half2_rn(v0.x, v0.y);
            *reinterpret_cast<__half2*>(g_V + ((size_t)(i*4+1)*NTIL + t)*256 + 2*c2) = __floats2half2_rn(v1.x, v1.y);
            *reinterpret_cast<__half2*>(g_V + ((size_t)(i*4+2)*NTIL + t)*256 + 2*c2) = __floats2half2_rn(v2.x, v2.y);
            *reinterpret_cast<__half2*>(g_V + ((size_t)(i*4+3)*NTIL + t)*256 + 2*c2) = __floats2half2_rn(v3.x, v3.y);
        }
        if (k < 7) {
            #pragma unroll
            for (int i = 0; i < 4; ++i) {
                d[i][0] = d[i][2];
                d[i][1] = d[i][3];
                d[i][2] = ldcol(i, wbase + 2 * k + 4);
                d[i][3] = ldcol(i, wbase + 2 * k + 5);
            }
        }
    }
}

// ============================================================================
// Kernel 2: weight transform U = G g Gt. grid=512 (n), block=256 (c).
// ============================================================================
__global__ void wino_w_kernel(const float* __restrict__ ws) {
    const int n = blockIdx.x;
    const int c = threadIdx.x;
    float g[3][3];
    #pragma unroll
    for (int kh = 0; kh < 3; ++kh)
        #pragma unroll
        for (int kw = 0; kw < 3; ++kw)
            g[kh][kw] = ws[((size_t)(kh * 3 + kw) * 256 + c) * 512 + n];
    float u[4][3];
    #pragma unroll
    for (int kw = 0; kw < 3; ++kw) {
        u[0][kw] = g[0][kw];
        u[1][kw] = 0.5f * (g[0][kw] + g[1][kw] + g[2][kw]);
        u[2][kw] = 0.5f * (g[0][kw] - g[1][kw] + g[2][kw]);
        u[3][kw] = g[2][kw];
    }
    #pragma unroll
    for (int r = 0; r < 4; ++r) {
        float U0 = u[r][0];
        float U1 = 0.5f * (u[r][0] + u[r][1] + u[r][2]);
        float U2 = 0.5f * (u[r][0] - u[r][1] + u[r][2]);
        float U3 = u[r][2];
        g_wU[((size_t)(r * 4 + 0) * 512 + n) * 256 + c] = __float2half(U0);
        g_wU[((size_t)(r * 4 + 1) * 512 + n) * 256 + c] = __float2half(U1);
        g_wU[((size_t)(r * 4 + 2) * 512 + n) * 256 + c] = __float2half(U2);
        g_wU[((size_t)(r * 4 + 3) * 512 + n) * 256 + c] = __float2half(U3);
    }
}

// ============================================================================
// Kernel 3: head weight pack (rows 90..127 zero).
// ============================================================================
__global__ void cvt_wh_kernel(const float* __restrict__ wc, const float* __restrict__ wr) {
    const int j = blockIdx.x;    // 0..127
    const int c = threadIdx.x;   // 0..511
    float v = 0.0f;
    if (j < 30)      v = wc[c * 30 + j];
    else if (j < 90) v = wr[c * 60 + (j - 30)];
    g_wh[(size_t)j * 512 + c] = __float2half(v);
}

// ============================================================================
// Kernel 4: persistent batched GEMM (proven 3-stage, 1 barrier/chunk).
// grid = 1024: mblk(256) x nhalf(2) x chalf(2). 512 thr, 16 warps (2m x 8n),
// warp 64x32, CTA 128x256. 8 comps x 4 chunks per CTA.
// ============================================================================
#define GW_STG     49152u
#define GW_A(s)    ((s) * GW_STG)
#define GW_B(s)    ((s) * GW_STG + 16384u)
#define GW_SMEM    147456
#define GW_NQQ     32

__global__ void __launch_bounds__(512, 1) wino_gemm_kernel()
{
    extern __shared__ char sm[];
    const uint32_t sb = smem_u32(sm);
    const int tid = threadIdx.x;
    const int mblk = blockIdx.x >> 2;
    const int n0 = ((blockIdx.x >> 1) & 1) << 8;
    const int c0 = (blockIdx.x & 1) << 3;
    const int t0 = mblk << 7;

    const int rowA = tid >> 2;
    const int kgA0 = (tid * 2) & 7;
    const int rowB = tid >> 1;
    const int kgB0 = (tid * 4) & 7;
    const uint32_t swA = (uint32_t)(rowA & 7);
    const uint32_t swB = (uint32_t)(rowB & 7);

    const int w = tid >> 5, l = tid & 31;
    const int wm = (w >> 3) * 64, wn = (w & 7) * 32;
    const int lrow = l & 15, hi = l >> 4;
    const uint32_t swL = (uint32_t)(lrow & 7);
    uint32_t aRow[4], bRow[2];
    #pragma unroll
    for (int mt = 0; mt < 4; ++mt) aRow[mt] = (uint32_t)((wm + mt * 16 + lrow) * 128);
    #pragma unroll
    for (int nt = 0; nt < 2; ++nt) bRow[nt] = (uint32_t)((wn + nt * 16 + lrow) * 128);

    float acc[4][4][4];
    #pragma unroll
    for (int mt = 0; mt < 4; ++mt)
        #pragma unroll
        for (int n8 = 0; n8 < 4; ++n8)
            #pragma unroll
            for (int e = 0; e < 4; ++e) acc[mt][n8][e] = 0.0f;

    auto load_chunk = [&](int qq, int s) {
        const int comp = c0 + (qq >> 2), q = qq & 3;
        const uint32_t Ab = sb + GW_A(s), Bb = sb + GW_B(s);
        const char* srcA = reinterpret_cast<const char*>(
            g_V + ((size_t)comp * NTIL + t0 + rowA) * 256 + q * 64);
        #pragma unroll
        for (int i = 0; i < 2; ++i) {
            const int kg = kgA0 + i;
            CP_ASYNC16(Ab + (uint32_t)rowA * 128 + (((uint32_t)kg ^ swA) << 4),
                       srcA + kg * 16, 16);
        }
        const char* srcB = reinterpret_cast<const char*>(
            g_wU + ((size_t)comp * 512 + n0 + rowB) * 256 + q * 64);
        #pragma unroll
        for (int i = 0; i < 4; ++i) {
            const int kg = kgB0 + i;
            CP_ASYNC16(Bb + (uint32_t)rowB * 128 + (((uint32_t)kg ^ swB) << 4),
                       srcB + kg * 16, 16);
        }
    };

    load_chunk(0, 0); CP_COMMIT();
    load_chunk(1, 1); CP_COMMIT();

    const int qrow = l >> 2, qcol = (l & 3) * 2;

    #pragma unroll 1
    for (int qq = 0; qq < GW_NQQ; ++qq) {
        if (qq + 1 < GW_NQQ) CP_WAIT1(); else CP_WAIT0();
        __syncthreads();
        if (qq + 2 < GW_NQQ) { load_chunk(qq + 2, (qq + 2) % 3); CP_COMMIT(); }

        const uint32_t Ab = sb + GW_A(qq % 3), Bb = sb + GW_B(qq % 3);
        #pragma unroll
        for (int ks = 0; ks < 4; ++ks) {
            const uint32_t col = (((uint32_t)(ks * 2 + hi)) ^ swL) << 4;
            uint32_t af[4][4], bf[2][4];
            #pragma unroll
            for (int mt = 0; mt < 4; ++mt) ldm4(af[mt], Ab + aRow[mt] + col);
            #pragma unroll
            for (int nt = 0; nt < 2; ++nt) ldm4(bf[nt], Bb + bRow[nt] + col);
            #pragma unroll
            for (int mt = 0; mt < 4; ++mt)
                #pragma unroll
                for (int n8 = 0; n8 < 4; ++n8)
                    mma16816(acc[mt][n8], af[mt], bf[n8 >> 1][n8 & 1], bf[n8 >> 1][(n8 & 1) + 2]);
        }

        if ((qq & 3) == 3) {
            const int comp = c0 + (qq >> 2);
            __half* Mb = g_M + ((size_t)comp * NTIL + t0) * 512 + n0;
            #pragma unroll
            for (int mt = 0; mt < 4; ++mt) {
                #pragma unroll
                for (int n8 = 0; n8 < 4; ++n8) {
                    const int ch = wn + n8 * 8 + qcol;
                    #pragma unroll
                    for (int hlf = 0; hlf < 2; ++hlf) {
                        const int m = wm + mt * 16 + qrow + hlf * 8;
                        *reinterpret_cast<__half2*>(Mb + (size_t)m * 512 + ch) =
                            __floats2half2_rn(acc[mt][n8][2 * hlf], acc[mt][n8][2 * hlf + 1]);
                        acc[mt][n8][2 * hlf] = 0.0f;
                        acc[mt][n8][2 * hlf + 1] = 0.0f;
                    }
                }
            }
        }
    }
}

// ============================================================================
// Kernel 5 (FUSED): output transform + head GEMM + softmax + writes.
// grid = 1024 CTAs x 256 thr; CTA owns 32 tiles = 128 positions.
// Per K-chunk q (64 ch): threads compute Y = At M A + bias, relu6 from g_M
// and store fp16 into the swizzled A smem tile; B via 2-stage cp.async;
// then the proven 8-warp (2m x 4n, 64x24) mma loop.
// SMEM: A 16KB + B 2x16KB + conv bias 2KB + head bias 512B = 51712 B.
// ============================================================================
#define FH_AB      0u
#define FH_B(buf)  (16384u + (buf) * 16384u)
#define FH_CBIAS   49152u
#define FH_HBIAS   51200u
#define FH_SMEM    51712
#define FH_NCH     8

__global__ void __launch_bounds__(256, 1) headfuse_kernel(const float* __restrict__ bs,
                                                          const float* __restrict__ bc,
                                                          const float* __restrict__ br,
                                                          float* __restrict__ out)
{
    extern __shared__ char sm[];
    const uint32_t sb = smem_u32(sm);
    const int tid = threadIdx.x;
    const int t0 = blockIdx.x * 32;

    float* cb = reinterpret_cast<float*>(sm + FH_CBIAS);   // conv bias [512]
    float* hb = reinterpret_cast<float*>(sm + FH_HBIAS);   // head bias [128]
    #pragma unroll
    for (int i = 0; i < 2; ++i) cb[tid + 256 * i] = bs[tid + 256 * i];
    if (tid < 128)
        hb[tid] = (tid < 30) ? bc[tid] : (tid < 90 ? br[tid - 30] : 0.0f);

    // B loader: 128 rows x 8 x 16B groups, 2 thr/row, 4 groups each
    const int rowB = tid >> 1;
    const int kgB0 = (tid & 1) * 4;
    const uint32_t swB = (uint32_t)(rowB & 7);

    // warp geometry: 8 warps = 2(m) x 4(n), warp tile 64x24
    const int w = tid >> 5, l = tid & 31;
    const int wm = (w >> 2) * 64, wn = (w & 3) * 24;
    const int lrow = l & 15, hi = l >> 4;
    const uint32_t swL = (uint32_t)(lrow & 7);
    uint32_t aRow[4], bRow[2];
    #pragma unroll
    for (int mt = 0; mt < 4; ++mt) aRow[mt] = (uint32_t)((wm + mt * 16 + lrow) * 128);
    #pragma unroll
    for (int nt = 0; nt < 2; ++nt) bRow[nt] = (uint32_t)((wn + nt * 16 + lrow) * 128);

    float acc[4][3][4];
    #pragma unroll
    for (int mt = 0; mt < 4; ++mt)
        #pragma unroll
        for (int n8 = 0; n8 < 3; ++n8)
            #pragma unroll
            for (int e = 0; e < 4; ++e) acc[mt][n8][e] = 0.0f;

    auto load_B = [&](int q, int buf) {
        const uint32_t Bb = sb + FH_B(buf);
        const char* srcB = reinterpret_cast<const char*>(
            g_wh + (size_t)rowB * 512 + q * 64);
        #pragma unroll
        for (int i = 0; i < 4; ++i) {
            const int kg = kgB0 + i;
            CP_ASYNC16(Bb + (uint32_t)rowB * 128 + (((uint32_t)kg ^ swB) << 4),
                       srcB + kg * 16, 16);
        }
    };

    // produce A tile for chunk q: Y[128 rows][64 ch] fp16, swizzled
    auto produce_A = [&](int q) {
        const uint32_t Ab = sb + FH_AB;
        #pragma unroll
        for (int it = 0; it < 4; ++it) {
            const int item = tid + 256 * it;
            const int tl = item >> 5;            // 0..31
            const int c2 = item & 31;            // ch pair within chunk
            const int t = t0 + tl;
            const int ch = q * 64 + 2 * c2;
            const __half* Mp = g_M + (size_t)t * 512 + ch;

            float2 m[4][4];
            #pragma unroll
            for (int i = 0; i < 4; ++i)
                #pragma unroll
                for (int j = 0; j < 4; ++j)
                    m[i][j] = __half22float2(*reinterpret_cast<const __half2*>(
                        Mp + (size_t)(i * 4 + j) * NTIL * 512));

            float2 s[2][4];
            #pragma unroll
            for (int j = 0; j < 4; ++j) {
                s[0][j] = make_float2(m[0][j].x + m[1][j].x + m[2][j].x,
                                      m[0][j].y + m[1][j].y + m[2][j].y);
                s[1][j] = make_float2(m[1][j].x - m[2][j].x - m[3][j].x,
                                      m[1][j].y - m[2][j].y - m[3][j].y);
            }
            const float b0 = cb[ch], b1 = cb[ch + 1];
            const uint32_t colOff = (((uint32_t)(c2 >> 2)) << 4) ^ 0u;  // group<<4
            #pragma unroll
            for (int dy = 0; dy < 2; ++dy) {
                float2 y0 = make_float2(s[dy][0].x + s[dy][1].x + s[dy][2].x,
                                        s[dy][0].y + s[dy][1].y + s[dy][2].y);
                float2 y1 = make_float2(s[dy][1].x - s[dy][2].x - s[dy][3].x,
                                        s[dy][1].y - s[dy][2].y - s[dy][3].y);
                #pragma unroll
                for (int dx = 0; dx < 2; ++dx) {
                    const float2 yv = dx ? y1 : y0;
                    const float v0 = fminf(fmaxf(yv.x + b0, 0.0f), 6.0f);
                    const float v1 = fminf(fmaxf(yv.y + b1, 0.0f), 6.0f);
                    const int r = tl * 4 + dy * 2 + dx;
                    const uint32_t addr = Ab + (uint32_t)r * 128 +
                        ((colOff >> 4) ^ (uint32_t)(r & 7)) * 16 + ((uint32_t)c2 & 3) * 4;
                    __half2 hv = __floats2half2_rn(v0, v1);
                    *reinterpret_cast<__half2*>(sm + (addr - sb)) = hv;
                }
            }
        }
    };

    load_B(0, 0); CP_COMMIT();

    #pragma unroll 1
    for (int q = 0; q < FH_NCH; ++q) {
        produce_A(q);
        if (q + 1 < FH_NCH) { load_B(q + 1, (q + 1) & 1); CP_COMMIT(); CP_WAIT1(); }
        else CP_WAIT0();
        __syncthreads();     // A stores visible + B(q) ready

        const uint32_t Ab = sb + FH_AB, Bb = sb + FH_B(q & 1);
        #pragma unroll
        for (int ks = 0; ks < 4; ++ks) {
            const uint32_t col = (((uint32_t)(ks * 2 + hi)) ^ swL) << 4;
            uint32_t af[4][4], bf[2][4];
            #pragma unroll
            for (int mt = 0; mt < 4; ++mt) ldm4(af[mt], Ab + aRow[mt] + col);
            #pragma unroll
            for (int nt = 0; nt < 2; ++nt) ldm4(bf[nt], Bb + bRow[nt] + col);
            #pragma unroll
            for (int mt = 0; mt < 4; ++mt)
                #pragma unroll
                for (int n8 = 0; n8 < 3; ++n8)
                    mma16816(acc[mt][n8], af[mt], bf[n8 >> 1][n8 & 1], bf[n8 >> 1][(n8 & 1) + 2]);
        }
        __syncthreads();     // before next produce overwrites A
    }

    // epilogue: row -> (tile, dy, dx) -> global position
    const int qrow = l >> 2, qcol = (l & 3) * 2;
    #pragma unroll
    for (int mt = 0; mt < 4; ++mt) {
        #pragma unroll
        for (int n8 = 0; n8 < 3; ++n8) {
            const int ch = wn + n8 * 8 + qcol;
            if (ch >= 90) continue;
            const float b0 = hb[ch], b1 = hb[ch + 1];
            #pragma unroll
            for (int hlf = 0; hlf < 2; ++hlf) {
                const int m = wm + mt * 16 + qrow + hlf * 8;
                const int tl = m >> 2, dy = (m >> 1) & 1, dx = m & 1;
                const int t = t0 + tl;
                const size_t pos =
                    ((size_t)((t >> 12) * 128 + 2 * ((t >> 6) & 63) + dy)) * 128
                    + 2 * (t & 63) + dx;
                const float v0 = acc[mt][n8][2 * hlf]     + b0;
                const float v1 = acc[mt][n8][2 * hlf + 1] + b1;
                if (ch < 30) {
                    *reinterpret_cast<float2*>(out + pos * 30 + ch) = make_float2(v0, v1);
                    const float mx = fmaxf(v0, v1);
                    const float e0 = __expf(v0 - mx), e1 = __expf(v1 - mx);
                    const float inv = 1.0f / (e0 + e1);
                    *reinterpret_cast<float2*>(out + OFF_PROBS + pos * 30 + ch) =
                        make_float2(e0 * inv, e1 * inv);
                } else {
                    *reinterpret_cast<float2*>(out + OFF_DELTAS + pos * 60 + (ch - 30)) =
                        make_float2(v0, v1);
                }
            }
        }
    }
}

// ============================================================================
// Launch
// ============================================================================
extern "C" void kernel_launch(void* const* d_in, const int* in_sizes, int n_in,
                              void* d_out, int out_size) {
    const float* x  = (const float*)d_in[0];
    const float* ws = (const float*)d_in[1];
    const float* bs = (const float*)d_in[2];
    const float* wc = (const float*)d_in[3];
    const float* bc = (const float*)d_in[4];
    const float* wr = (const float*)d_in[5];
    const float* br = (const float*)d_in[6];
    float* out = (float*)d_out;

    cudaFuncSetAttribute(wino_gemm_kernel, cudaFuncAttributeMaxDynamicSharedMemorySize, GW_SMEM);
    cudaFuncSetAttribute(headfuse_kernel, cudaFuncAttributeMaxDynamicSharedMemorySize, FH_SMEM);

    wino_in_kernel<<<4096, 128>>>(x);
    wino_w_kernel<<<512, 256>>>(ws);
    cvt_wh_kernel<<<128, 512>>>(wc, wr);
    wino_gemm_kernel<<<1024, 512, GW_SMEM>>>();
    headfuse_kernel<<<1024, 256, FH_SMEM>>>(bs, bc, br, out);
}

// round 15
// speedup vs baseline: 1.0123x; 1.0123x over previous
#include <cuda_runtime.h>
#include <cuda_fp16.h>
#include <cstdint>

// ============================================================================
// RPNHead via Winograd F(2x2,3x3). R15 = R14 with the fused head kernel at
// 2 CTAs/SM (__launch_bounds__(256,2)): co-resident CTAs overlap the
// latency-bound produce_A phase with the other CTA's mma phase.
// ============================================================================
#define NPOS 131072
#define NTIL 32768
#define OFF_PROBS  3932160
#define OFF_DELTAS 7864320

__device__ __align__(1024) __half g_V [(size_t)16*NTIL*256];   // input transform
__device__ __align__(1024) __half g_wU[(size_t)16*512*256];    // weight transform
__device__ __align__(1024) __half g_M [(size_t)16*NTIL*512];   // GEMM results (fp16)
__device__ __align__(1024) __half g_wh[(size_t)128*512];       // head W [j][c]

__device__ __forceinline__ uint32_t smem_u32(const void* p) {
    uint32_t a;
    asm("{ .reg .u64 t; cvta.to.shared.u64 t, %1; cvt.u32.u64 %0, t; }"
        : "=r"(a) : "l"(p));
    return a;
}

#define CP_ASYNC16(dst, src, sz) \
    asm volatile("cp.async.cg.shared.global [%0], [%1], 16, %2;" \
        :: "r"((uint32_t)(dst)), "l"(src), "r"((int)(sz)) : "memory")
#define CP_COMMIT() asm volatile("cp.async.commit_group;" ::: "memory")
#define CP_WAIT1()  asm volatile("cp.async.wait_group 1;" ::: "memory")
#define CP_WAIT0()  asm volatile("cp.async.wait_group 0;" ::: "memory")

__device__ __forceinline__ void ldm4(uint32_t* f, uint32_t addr) {
    asm volatile("ldmatrix.sync.aligned.m8n8.x4.shared.b16 {%0,%1,%2,%3}, [%4];"
        : "=r"(f[0]), "=r"(f[1]), "=r"(f[2]), "=r"(f[3]) : "r"(addr));
}
__device__ __forceinline__ void mma16816(float* c, const uint32_t* a,
                                         uint32_t b0, uint32_t b1) {
    asm volatile("mma.sync.aligned.m16n8k16.row.col.f32.f16.f16.f32 "
        "{%0,%1,%2,%3}, {%4,%5,%6,%7}, {%8,%9}, {%0,%1,%2,%3};"
        : "+f"(c[0]), "+f"(c[1]), "+f"(c[2]), "+f"(c[3])
        : "r"(a[0]), "r"(a[1]), "r"(a[2]), "r"(a[3]), "r"(b0), "r"(b1));
}

// ============================================================================
// Kernel 1: input transform V = Bt d B, 8 tiles per block, sliding window.
// ============================================================================
__global__ void wino_in_kernel(const float* __restrict__ x) {
    const int blk = blockIdx.x;
    const int wgrp = blk & 7;
    const int th = (blk >> 3) & 63;
    const int b = blk >> 9;
    const int c2 = threadIdx.x;
    const int tw0 = wgrp * 8;
    const int h0 = th * 2 - 1;
    const int wbase = tw0 * 2 - 1;

    bool hv[4];
    const float* rowp[4];
    #pragma unroll
    for (int i = 0; i < 4; ++i) {
        const int h = h0 + i;
        hv[i] = (h >= 0) && (h < 128);
        rowp[i] = x + ((size_t)((b * 128 + (hv[i] ? h : 0)) * 128)) * 256 + 2 * c2;
    }

    auto ldcol = [&](int i, int wc) -> float2 {
        if (hv[i] && wc >= 0 && wc < 128)
            return *reinterpret_cast<const float2*>(rowp[i] + (size_t)wc * 256);
        return make_float2(0.0f, 0.0f);
    };

    float2 d[4][4];
    #pragma unroll
    for (int i = 0; i < 4; ++i)
        #pragma unroll
        for (int j = 0; j < 4; ++j)
            d[i][j] = ldcol(i, wbase + j);

    #pragma unroll
    for (int k = 0; k < 8; ++k) {
        const int t = (b * 64 + th) * 64 + (tw0 + k);
        float2 tr[4][4];
        #pragma unroll
        for (int j = 0; j < 4; ++j) {
            tr[0][j] = make_float2(d[0][j].x - d[2][j].x, d[0][j].y - d[2][j].y);
            tr[1][j] = make_float2(d[1][j].x + d[2][j].x, d[1][j].y + d[2][j].y);
            tr[2][j] = make_float2(d[2][j].x - d[1][j].x, d[2][j].y - d[1][j].y);
            tr[3][j] = make_float2(d[1][j].x - d[3][j].x, d[1][j].y - d[3][j].y);
        }
        #pragma unroll
        for (int i = 0; i < 4; ++i) {
            float2 v0 = make_float2(tr[i][0].x - tr[i][2].x, tr[i][0].y - tr[i][2].y);
            float2 v1 = make_float2(tr[i][1].x + tr[i][2].x, tr[i][1].y + tr[i][2].y);
            float2 v2 = make_float2(tr[i][2].x - tr[i][1].x, tr[i][2].y - tr[i][1].y);
            float2 v3 = make_float2(tr[i][1].x - tr[i][3].x, tr[i][1].y - tr[i][3].y);
            *reinterpret_cast<__half2*>(g_V + ((size_t)(i*4+0)*NTIL + t)*256 + 2*c2) = __floats2half2_rn(v0.x, v0.y);
            *reinterpret_cast<__half2*>(g_V + ((size_t)(i*4+1)*NTIL + t)*256 + 2*c2) = __floats2half2_rn(v1.x, v1.y);
            *reinterpret_cast<__half2*>(g_V + ((size_t)(i*4+2)*NTIL + t)*256 + 2*c2) = __floats2half2_rn(v2.x, v2.y);
            *reinterpret_cast<__half2*>(g_V + ((size_t)(i*4+3)*NTIL + t)*256 + 2*c2) = __floats2half2_rn(v3.x, v3.y);
        }
        if (k < 7) {
            #pragma unroll
            for (int i = 0; i < 4; ++i) {
                d[i][0] = d[i][2];
                d[i][1] = d[i][3];
                d[i][2] = ldcol(i, wbase + 2 * k + 4);
                d[i][3] = ldcol(i, wbase + 2 * k + 5);
            }
        }
    }
}

// ============================================================================
// Kernel 2: weight transform U = G g Gt. grid=512 (n), block=256 (c).
// ============================================================================
__global__ void wino_w_kernel(const float* __restrict__ ws) {
    const int n = blockIdx.x;
    const int c = threadIdx.x;
    float g[3][3];
    #pragma unroll
    for (int kh = 0; kh < 3; ++kh)
        #pragma unroll
        for (int kw = 0; kw < 3; ++kw)
            g[kh][kw] = ws[((size_t)(kh * 3 + kw) * 256 + c) * 512 + n];
    float u[4][3];
    #pragma unroll
    for (int kw = 0; kw < 3; ++kw) {
        u[0][kw] = g[0][kw];
        u[1][kw] = 0.5f * (g[0][kw] + g[1][kw] + g[2][kw]);
        u[2][kw] = 0.5f * (g[0][kw] - g[1][kw] + g[2][kw]);
        u[3][kw] = g[2][kw];
    }
    #pragma unroll
    for (int r = 0; r < 4; ++r) {
        float U0 = u[r][0];
        float U1 = 0.5f * (u[r][0] + u[r][1] + u[r][2]);
        float U2 = 0.5f * (u[r][0] - u[r][1] + u[r][2]);
        float U3 = u[r][2];
        g_wU[((size_t)(r * 4 + 0) * 512 + n) * 256 + c] = __float2half(U0);
        g_wU[((size_t)(r * 4 + 1) * 512 + n) * 256 + c] = __float2half(U1);
        g_wU[((size_t)(r * 4 + 2) * 512 + n) * 256 + c] = __float2half(U2);
        g_wU[((size_t)(r * 4 + 3) * 512 + n) * 256 + c] = __float2half(U3);
    }
}

// ============================================================================
// Kernel 3: head weight pack (rows 90..127 zero).
// ============================================================================
__global__ void cvt_wh_kernel(const float* __restrict__ wc, const float* __restrict__ wr) {
    const int j = blockIdx.x;    // 0..127
    const int c = threadIdx.x;   // 0..511
    float v = 0.0f;
    if (j < 30)      v = wc[c * 30 + j];
    else if (j < 90) v = wr[c * 60 + (j - 30)];
    g_wh[(size_t)j * 512 + c] = __float2half(v);
}

// ============================================================================
// Kernel 4: persistent batched GEMM (proven 3-stage, 1 barrier/chunk).
// ============================================================================
#define GW_STG     49152u
#define GW_A(s)    ((s) * GW_STG)
#define GW_B(s)    ((s) * GW_STG + 16384u)
#define GW_SMEM    147456
#define GW_NQQ     32

__global__ void __launch_bounds__(512, 1) wino_gemm_kernel()
{
    extern __shared__ char sm[];
    const uint32_t sb = smem_u32(sm);
    const int tid = threadIdx.x;
    const int mblk = blockIdx.x >> 2;
    const int n0 = ((blockIdx.x >> 1) & 1) << 8;
    const int c0 = (blockIdx.x & 1) << 3;
    const int t0 = mblk << 7;

    const int rowA = tid >> 2;
    const int kgA0 = (tid * 2) & 7;
    const int rowB = tid >> 1;
    const int kgB0 = (tid * 4) & 7;
    const uint32_t swA = (uint32_t)(rowA & 7);
    const uint32_t swB = (uint32_t)(rowB & 7);

    const int w = tid >> 5, l = tid & 31;
    const int wm = (w >> 3) * 64, wn = (w & 7) * 32;
    const int lrow = l & 15, hi = l >> 4;
    const uint32_t swL = (uint32_t)(lrow & 7);
    uint32_t aRow[4], bRow[2];
    #pragma unroll
    for (int mt = 0; mt < 4; ++mt) aRow[mt] = (uint32_t)((wm + mt * 16 + lrow) * 128);
    #pragma unroll
    for (int nt = 0; nt < 2; ++nt) bRow[nt] = (uint32_t)((wn + nt * 16 + lrow) * 128);

    float acc[4][4][4];
    #pragma unroll
    for (int mt = 0; mt < 4; ++mt)
        #pragma unroll
        for (int n8 = 0; n8 < 4; ++n8)
            #pragma unroll
            for (int e = 0; e < 4; ++e) acc[mt][n8][e] = 0.0f;

    auto load_chunk = [&](int qq, int s) {
        const int comp = c0 + (qq >> 2), q = qq & 3;
        const uint32_t Ab = sb + GW_A(s), Bb = sb + GW_B(s);
        const char* srcA = reinterpret_cast<const char*>(
            g_V + ((size_t)comp * NTIL + t0 + rowA) * 256 + q * 64);
        #pragma unroll
        for (int i = 0; i < 2; ++i) {
            const int kg = kgA0 + i;
            CP_ASYNC16(Ab + (uint32_t)rowA * 128 + (((uint32_t)kg ^ swA) << 4),
                       srcA + kg * 16, 16);
        }
        const char* srcB = reinterpret_cast<const char*>(
            g_wU + ((size_t)comp * 512 + n0 + rowB) * 256 + q * 64);
        #pragma unroll
        for (int i = 0; i < 4; ++i) {
            const int kg = kgB0 + i;
            CP_ASYNC16(Bb + (uint32_t)rowB * 128 + (((uint32_t)kg ^ swB) << 4),
                       srcB + kg * 16, 16);
        }
    };

    load_chunk(0, 0); CP_COMMIT();
    load_chunk(1, 1); CP_COMMIT();

    const int qrow = l >> 2, qcol = (l & 3) * 2;

    #pragma unroll 1
    for (int qq = 0; qq < GW_NQQ; ++qq) {
        if (qq + 1 < GW_NQQ) CP_WAIT1(); else CP_WAIT0();
        __syncthreads();
        if (qq + 2 < GW_NQQ) { load_chunk(qq + 2, (qq + 2) % 3); CP_COMMIT(); }

        const uint32_t Ab = sb + GW_A(qq % 3), Bb = sb + GW_B(qq % 3);
        #pragma unroll
        for (int ks = 0; ks < 4; ++ks) {
            const uint32_t col = (((uint32_t)(ks * 2 + hi)) ^ swL) << 4;
            uint32_t af[4][4], bf[2][4];
            #pragma unroll
            for (int mt = 0; mt < 4; ++mt) ldm4(af[mt], Ab + aRow[mt] + col);
            #pragma unroll
            for (int nt = 0; nt < 2; ++nt) ldm4(bf[nt], Bb + bRow[nt] + col);
            #pragma unroll
            for (int mt = 0; mt < 4; ++mt)
                #pragma unroll
                for (int n8 = 0; n8 < 4; ++n8)
                    mma16816(acc[mt][n8], af[mt], bf[n8 >> 1][n8 & 1], bf[n8 >> 1][(n8 & 1) + 2]);
        }

        if ((qq & 3) == 3) {
            const int comp = c0 + (qq >> 2);
            __half* Mb = g_M + ((size_t)comp * NTIL + t0) * 512 + n0;
            #pragma unroll
            for (int mt = 0; mt < 4; ++mt) {
                #pragma unroll
                for (int n8 = 0; n8 < 4; ++n8) {
                    const int ch = wn + n8 * 8 + qcol;
                    #pragma unroll
                    for (int hlf = 0; hlf < 2; ++hlf) {
                        const int m = wm + mt * 16 + qrow + hlf * 8;
                        *reinterpret_cast<__half2*>(Mb + (size_t)m * 512 + ch) =
                            __floats2half2_rn(acc[mt][n8][2 * hlf], acc[mt][n8][2 * hlf + 1]);
                        acc[mt][n8][2 * hlf] = 0.0f;
                        acc[mt][n8][2 * hlf + 1] = 0.0f;
                    }
                }
            }
        }
    }
}

// ============================================================================
// Kernel 5 (FUSED): output transform + head GEMM + softmax + writes.
// 2 CTAs/SM via __launch_bounds__(256, 2).
// ============================================================================
#define FH_AB      0u
#define FH_B(buf)  (16384u + (buf) * 16384u)
#define FH_CBIAS   49152u
#define FH_HBIAS   51200u
#define FH_SMEM    51712
#define FH_NCH     8

__global__ void __launch_bounds__(256, 2) headfuse_kernel(const float* __restrict__ bs,
                                                          const float* __restrict__ bc,
                                                          const float* __restrict__ br,
                                                          float* __restrict__ out)
{
    extern __shared__ char sm[];
    const uint32_t sb = smem_u32(sm);
    const int tid = threadIdx.x;
    const int t0 = blockIdx.x * 32;

    float* cb = reinterpret_cast<float*>(sm + FH_CBIAS);   // conv bias [512]
    float* hb = reinterpret_cast<float*>(sm + FH_HBIAS);   // head bias [128]
    #pragma unroll
    for (int i = 0; i < 2; ++i) cb[tid + 256 * i] = bs[tid + 256 * i];
    if (tid < 128)
        hb[tid] = (tid < 30) ? bc[tid] : (tid < 90 ? br[tid - 30] : 0.0f);

    const int rowB = tid >> 1;
    const int kgB0 = (tid & 1) * 4;
    const uint32_t swB = (uint32_t)(rowB & 7);

    const int w = tid >> 5, l = tid & 31;
    const int wm = (w >> 2) * 64, wn = (w & 3) * 24;
    const int lrow = l & 15, hi = l >> 4;
    const uint32_t swL = (uint32_t)(lrow & 7);
    uint32_t aRow[4], bRow[2];
    #pragma unroll
    for (int mt = 0; mt < 4; ++mt) aRow[mt] = (uint32_t)((wm + mt * 16 + lrow) * 128);
    #pragma unroll
    for (int nt = 0; nt < 2; ++nt) bRow[nt] = (uint32_t)((wn + nt * 16 + lrow) * 128);

    float acc[4][3][4];
    #pragma unroll
    for (int mt = 0; mt < 4; ++mt)
        #pragma unroll
        for (int n8 = 0; n8 < 3; ++n8)
            #pragma unroll
            for (int e = 0; e < 4; ++e) acc[mt][n8][e] = 0.0f;

    auto load_B = [&](int q, int buf) {
        const uint32_t Bb = sb + FH_B(buf);
        const char* srcB = reinterpret_cast<const char*>(
            g_wh + (size_t)rowB * 512 + q * 64);
        #pragma unroll
        for (int i = 0; i < 4; ++i) {
            const int kg = kgB0 + i;
            CP_ASYNC16(Bb + (uint32_t)rowB * 128 + (((uint32_t)kg ^ swB) << 4),
                       srcB + kg * 16, 16);
        }
    };

    auto produce_A = [&](int q) {
        const uint32_t Ab = sb + FH_AB;
        #pragma unroll
        for (int it = 0; it < 4; ++it) {
            const int item = tid + 256 * it;
            const int tl = item >> 5;            // 0..31
            const int c2 = item & 31;            // ch pair within chunk
            const int t = t0 + tl;
            const int ch = q * 64 + 2 * c2;
            const __half* Mp = g_M + (size_t)t * 512 + ch;

            float2 m[4][4];
            #pragma unroll
            for (int i = 0; i < 4; ++i)
                #pragma unroll
                for (int j = 0; j < 4; ++j)
                    m[i][j] = __half22float2(*reinterpret_cast<const __half2*>(
                        Mp + (size_t)(i * 4 + j) * NTIL * 512));

            float2 s[2][4];
            #pragma unroll
            for (int j = 0; j < 4; ++j) {
                s[0][j] = make_float2(m[0][j].x + m[1][j].x + m[2][j].x,
                                      m[0][j].y + m[1][j].y + m[2][j].y);
                s[1][j] = make_float2(m[1][j].x - m[2][j].x - m[3][j].x,
                                      m[1][j].y - m[2][j].y - m[3][j].y);
            }
            const float b0 = cb[ch], b1 = cb[ch + 1];
            const uint32_t grp = (uint32_t)(c2 >> 2);
            #pragma unroll
            for (int dy = 0; dy < 2; ++dy) {
                float2 y0 = make_float2(s[dy][0].x + s[dy][1].x + s[dy][2].x,
                                        s[dy][0].y + s[dy][1].y + s[dy][2].y);
                float2 y1 = make_float2(s[dy][1].x - s[dy][2].x - s[dy][3].x,
                                        s[dy][1].y - s[dy][2].y - s[dy][3].y);
                #pragma unroll
                for (int dx = 0; dx < 2; ++dx) {
                    const float2 yv = dx ? y1 : y0;
                    const float v0 = fminf(fmaxf(yv.x + b0, 0.0f), 6.0f);
                    const float v1 = fminf(fmaxf(yv.y + b1, 0.0f), 6.0f);
                    const int r = tl * 4 + dy * 2 + dx;
                    const uint32_t off = (uint32_t)r * 128 +
                        (grp ^ (uint32_t)(r & 7)) * 16 + ((uint32_t)c2 & 3) * 4;
                    *reinterpret_cast<__half2*>(sm + FH_AB + off) =
                        __floats2half2_rn(v0, v1);
                }
            }
        }
    };

    load_B(0, 0); CP_COMMIT();

    #pragma unroll 1
    for (int q = 0; q < FH_NCH; ++q) {
        produce_A(q);
        if (q + 1 < FH_NCH) { load_B(q + 1, (q + 1) & 1); CP_COMMIT(); CP_WAIT1(); }
        else CP_WAIT0();
        __syncthreads();

        const uint32_t Ab = sb + FH_AB, Bb = sb + FH_B(q & 1);
        #pragma unroll
        for (int ks = 0; ks < 4; ++ks) {
            const uint32_t col = (((uint32_t)(ks * 2 + hi)) ^ swL) << 4;
            uint32_t af[4][4], bf[2][4];
            #pragma unroll
            for (int mt = 0; mt < 4; ++mt) ldm4(af[mt], Ab + aRow[mt] + col);
            #pragma unroll
            for (int nt = 0; nt < 2; ++nt) ldm4(bf[nt], Bb + bRow[nt] + col);
            #pragma unroll
            for (int mt = 0; mt < 4; ++mt)
                #pragma unroll
                for (int n8 = 0; n8 < 3; ++n8)
                    mma16816(acc[mt][n8], af[mt], bf[n8 >> 1][n8 & 1], bf[n8 >> 1][(n8 & 1) + 2]);
        }
        __syncthreads();
    }

    const int qrow = l >> 2, qcol = (l & 3) * 2;
    #pragma unroll
    for (int mt = 0; mt < 4; ++mt) {
        #pragma unroll
        for (int n8 = 0; n8 < 3; ++n8) {
            const int ch = wn + n8 * 8 + qcol;
            if (ch >= 90) continue;
            const float b0 = hb[ch], b1 = hb[ch + 1];
            #pragma unroll
            for (int hlf = 0; hlf < 2; ++hlf) {
                const int m = wm + mt * 16 + qrow + hlf * 8;
                const int tl = m >> 2, dy = (m >> 1) & 1, dx = m & 1;
                const int t = t0 + tl;
                const size_t pos =
                    ((size_t)((t >> 12) * 128 + 2 * ((t >> 6) & 63) + dy)) * 128
                    + 2 * (t & 63) + dx;
                const float v0 = acc[mt][n8][2 * hlf]     + b0;
                const float v1 = acc[mt][n8][2 * hlf + 1] + b1;
                if (ch < 30) {
                    *reinterpret_cast<float2*>(out + pos * 30 + ch) = make_float2(v0, v1);
                    const float mx = fmaxf(v0, v1);
                    const float e0 = __expf(v0 - mx), e1 = __expf(v1 - mx);
                    const float inv = 1.0f / (e0 + e1);
                    *reinterpret_cast<float2*>(out + OFF_PROBS + pos * 30 + ch) =
                        make_float2(e0 * inv, e1 * inv);
                } else {
                    *reinterpret_cast<float2*>(out + OFF_DELTAS + pos * 60 + (ch - 30)) =
                        make_float2(v0, v1);
                }
            }
        }
    }
}

// ============================================================================
// Launch
// ============================================================================
extern "C" void kernel_launch(void* const* d_in, const int* in_sizes, int n_in,
                              void* d_out, int out_size) {
    const float* x  = (const float*)d_in[0];
    const float* ws = (const float*)d_in[1];
    const float* bs = (const float*)d_in[2];
    const float* wc = (const float*)d_in[3];
    const float* bc = (const float*)d_in[4];
    const float* wr = (const float*)d_in[5];
    const float* br = (const float*)d_in[6];
    float* out = (float*)d_out;

    cudaFuncSetAttribute(wino_gemm_kernel, cudaFuncAttributeMaxDynamicSharedMemorySize, GW_SMEM);
    cudaFuncSetAttribute(headfuse_kernel, cudaFuncAttributeMaxDynamicSharedMemorySize, FH_SMEM);

    wino_in_kernel<<<4096, 128>>>(x);
    wino_w_kernel<<<512, 256>>>(ws);
    cvt_wh_kernel<<<128, 512>>>(wc, wr);
    wino_gemm_kernel<<<1024, 512, GW_SMEM>>>();
    headfuse_kernel<<<1024, 256, FH_SMEM>>>(bs, bc, br, out);
}

// round 16
// speedup vs baseline: 1.0245x; 1.0121x over previous
#include <cuda_runtime.h>
#include <cuda_fp16.h>
#include <cstdint>

// ============================================================================
// RPNHead via Winograd F(2x2,3x3). R16 = R15 (fused out-transform+head,
// 2 CTAs/SM) with g_M re-laid out as [tile][comp][ch]: each tile's 16
// components are contiguous (16KB), fixing produce_A's 32MB-stride reads.
// ============================================================================
#define NPOS 131072
#define NTIL 32768
#define OFF_PROBS  3932160
#define OFF_DELTAS 7864320

__device__ __align__(1024) __half g_V [(size_t)16*NTIL*256];   // input transform
__device__ __align__(1024) __half g_wU[(size_t)16*512*256];    // weight transform
__device__ __align__(1024) __half g_M [(size_t)NTIL*16*512];   // [tile][comp][ch]
__device__ __align__(1024) __half g_wh[(size_t)128*512];       // head W [j][c]

__device__ __forceinline__ uint32_t smem_u32(const void* p) {
    uint32_t a;
    asm("{ .reg .u64 t; cvta.to.shared.u64 t, %1; cvt.u32.u64 %0, t; }"
        : "=r"(a) : "l"(p));
    return a;
}

#define CP_ASYNC16(dst, src, sz) \
    asm volatile("cp.async.cg.shared.global [%0], [%1], 16, %2;" \
        :: "r"((uint32_t)(dst)), "l"(src), "r"((int)(sz)) : "memory")
#define CP_COMMIT() asm volatile("cp.async.commit_group;" ::: "memory")
#define CP_WAIT1()  asm volatile("cp.async.wait_group 1;" ::: "memory")
#define CP_WAIT0()  asm volatile("cp.async.wait_group 0;" ::: "memory")

__device__ __forceinline__ void ldm4(uint32_t* f, uint32_t addr) {
    asm volatile("ldmatrix.sync.aligned.m8n8.x4.shared.b16 {%0,%1,%2,%3}, [%4];"
        : "=r"(f[0]), "=r"(f[1]), "=r"(f[2]), "=r"(f[3]) : "r"(addr));
}
__device__ __forceinline__ void mma16816(float* c, const uint32_t* a,
                                         uint32_t b0, uint32_t b1) {
    asm volatile("mma.sync.aligned.m16n8k16.row.col.f32.f16.f16.f32 "
        "{%0,%1,%2,%3}, {%4,%5,%6,%7}, {%8,%9}, {%0,%1,%2,%3};"
        : "+f"(c[0]), "+f"(c[1]), "+f"(c[2]), "+f"(c[3])
        : "r"(a[0]), "r"(a[1]), "r"(a[2]), "r"(a[3]), "r"(b0), "r"(b1));
}

// ============================================================================
// Kernel 1: input transform V = Bt d B, 8 tiles per block, sliding window.
// ============================================================================
__global__ void wino_in_kernel(const float* __restrict__ x) {
    const int blk = blockIdx.x;
    const int wgrp = blk & 7;
    const int th = (blk >> 3) & 63;
    const int b = blk >> 9;
    const int c2 = threadIdx.x;
    const int tw0 = wgrp * 8;
    const int h0 = th * 2 - 1;
    const int wbase = tw0 * 2 - 1;

    bool hv[4];
    const float* rowp[4];
    #pragma unroll
    for (int i = 0; i < 4; ++i) {
        const int h = h0 + i;
        hv[i] = (h >= 0) && (h < 128);
        rowp[i] = x + ((size_t)((b * 128 + (hv[i] ? h : 0)) * 128)) * 256 + 2 * c2;
    }

    auto ldcol = [&](int i, int wc) -> float2 {
        if (hv[i] && wc >= 0 && wc < 128)
            return *reinterpret_cast<const float2*>(rowp[i] + (size_t)wc * 256);
        return make_float2(0.0f, 0.0f);
    };

    float2 d[4][4];
    #pragma unroll
    for (int i = 0; i < 4; ++i)
        #pragma unroll
        for (int j = 0; j < 4; ++j)
            d[i][j] = ldcol(i, wbase + j);

    #pragma unroll
    for (int k = 0; k < 8; ++k) {
        const int t = (b * 64 + th) * 64 + (tw0 + k);
        float2 tr[4][4];
        #pragma unroll
        for (int j = 0; j < 4; ++j) {
            tr[0][j] = make_float2(d[0][j].x - d[2][j].x, d[0][j].y - d[2][j].y);
            tr[1][j] = make_float2(d[1][j].x + d[2][j].x, d[1][j].y + d[2][j].y);
            tr[2][j] = make_float2(d[2][j].x - d[1][j].x, d[2][j].y - d[1][j].y);
            tr[3][j] = make_float2(d[1][j].x - d[3][j].x, d[1][j].y - d[3][j].y);
        }
        #pragma unroll
        for (int i = 0; i < 4; ++i) {
            float2 v0 = make_float2(tr[i][0].x - tr[i][2].x, tr[i][0].y - tr[i][2].y);
            float2 v1 = make_float2(tr[i][1].x + tr[i][2].x, tr[i][1].y + tr[i][2].y);
            float2 v2 = make_float2(tr[i][2].x - tr[i][1].x, tr[i][2].y - tr[i][1].y);
            float2 v3 = make_float2(tr[i][1].x - tr[i][3].x, tr[i][1].y - tr[i][3].y);
            *reinterpret_cast<__half2*>(g_V + ((size_t)(i*4+0)*NTIL + t)*256 + 2*c2) = __floats2half2_rn(v0.x, v0.y);
            *reinterpret_cast<__half2*>(g_V + ((size_t)(i*4+1)*NTIL + t)*256 + 2*c2) = __floats2half2_rn(v1.x, v1.y);
            *reinterpret_cast<__half2*>(g_V + ((size_t)(i*4+2)*NTIL + t)*256 + 2*c2) = __floats2half2_rn(v2.x, v2.y);
            *reinterpret_cast<__half2*>(g_V + ((size_t)(i*4+3)*NTIL + t)*256 + 2*c2) = __floats2half2_rn(v3.x, v3.y);
        }
        if (k < 7) {
            #pragma unroll
            for (int i = 0; i < 4; ++i) {
                d[i][0] = d[i][2];
                d[i][1] = d[i][3];
                d[i][2] = ldcol(i, wbase + 2 * k + 4);
                d[i][3] = ldcol(i, wbase + 2 * k + 5);
            }
        }
    }
}

// ============================================================================
// Kernel 2: weight transform U = G g Gt. grid=512 (n), block=256 (c).
// ============================================================================
__global__ void wino_w_kernel(const float* __restrict__ ws) {
    const int n = blockIdx.x;
    const int c = threadIdx.x;
    float g[3][3];
    #pragma unroll
    for (int kh = 0; kh < 3; ++kh)
        #pragma unroll
        for (int kw = 0; kw < 3; ++kw)
            g[kh][kw] = ws[((size_t)(kh * 3 + kw) * 256 + c) * 512 + n];
    float u[4][3];
    #pragma unroll
    for (int kw = 0; kw < 3; ++kw) {
        u[0][kw] = g[0][kw];
        u[1][kw] = 0.5f * (g[0][kw] + g[1][kw] + g[2][kw]);
        u[2][kw] = 0.5f * (g[0][kw] - g[1][kw] + g[2][kw]);
        u[3][kw] = g[2][kw];
    }
    #pragma unroll
    for (int r = 0; r < 4; ++r) {
        float U0 = u[r][0];
        float U1 = 0.5f * (u[r][0] + u[r][1] + u[r][2]);
        float U2 = 0.5f * (u[r][0] - u[r][1] + u[r][2]);
        float U3 = u[r][2];
        g_wU[((size_t)(r * 4 + 0) * 512 + n) * 256 + c] = __float2half(U0);
        g_wU[((size_t)(r * 4 + 1) * 512 + n) * 256 + c] = __float2half(U1);
        g_wU[((size_t)(r * 4 + 2) * 512 + n) * 256 + c] = __float2half(U2);
        g_wU[((size_t)(r * 4 + 3) * 512 + n) * 256 + c] = __float2half(U3);
    }
}

// ============================================================================
// Kernel 3: head weight pack (rows 90..127 zero).
// ============================================================================
__global__ void cvt_wh_kernel(const float* __restrict__ wc, const float* __restrict__ wr) {
    const int j = blockIdx.x;    // 0..127
    const int c = threadIdx.x;   // 0..511
    float v = 0.0f;
    if (j < 30)      v = wc[c * 30 + j];
    else if (j < 90) v = wr[c * 60 + (j - 30)];
    g_wh[(size_t)j * 512 + c] = __float2half(v);
}

// ============================================================================
// Kernel 4: persistent batched GEMM (proven 3-stage, 1 barrier/chunk).
// Epilogue writes g_M in [tile][comp][ch] layout.
// ============================================================================
#define GW_STG     49152u
#define GW_A(s)    ((s) * GW_STG)
#define GW_B(s)    ((s) * GW_STG + 16384u)
#define GW_SMEM    147456
#define GW_NQQ     32

__global__ void __launch_bounds__(512, 1) wino_gemm_kernel()
{
    extern __shared__ char sm[];
    const uint32_t sb = smem_u32(sm);
    const int tid = threadIdx.x;
    const int mblk = blockIdx.x >> 2;
    const int n0 = ((blockIdx.x >> 1) & 1) << 8;
    const int c0 = (blockIdx.x & 1) << 3;
    const int t0 = mblk << 7;

    const int rowA = tid >> 2;
    const int kgA0 = (tid * 2) & 7;
    const int rowB = tid >> 1;
    const int kgB0 = (tid * 4) & 7;
    const uint32_t swA = (uint32_t)(rowA & 7);
    const uint32_t swB = (uint32_t)(rowB & 7);

    const int w = tid >> 5, l = tid & 31;
    const int wm = (w >> 3) * 64, wn = (w & 7) * 32;
    const int lrow = l & 15, hi = l >> 4;
    const uint32_t swL = (uint32_t)(lrow & 7);
    uint32_t aRow[4], bRow[2];
    #pragma unroll
    for (int mt = 0; mt < 4; ++mt) aRow[mt] = (uint32_t)((wm + mt * 16 + lrow) * 128);
    #pragma unroll
    for (int nt = 0; nt < 2; ++nt) bRow[nt] = (uint32_t)((wn + nt * 16 + lrow) * 128);

    float acc[4][4][4];
    #pragma unroll
    for (int mt = 0; mt < 4; ++mt)
        #pragma unroll
        for (int n8 = 0; n8 < 4; ++n8)
            #pragma unroll
            for (int e = 0; e < 4; ++e) acc[mt][n8][e] = 0.0f;

    auto load_chunk = [&](int qq, int s) {
        const int comp = c0 + (qq >> 2), q = qq & 3;
        const uint32_t Ab = sb + GW_A(s), Bb = sb + GW_B(s);
        const char* srcA = reinterpret_cast<const char*>(
            g_V + ((size_t)comp * NTIL + t0 + rowA) * 256 + q * 64);
        #pragma unroll
        for (int i = 0; i < 2; ++i) {
            const int kg = kgA0 + i;
            CP_ASYNC16(Ab + (uint32_t)rowA * 128 + (((uint32_t)kg ^ swA) << 4),
                       srcA + kg * 16, 16);
        }
        const char* srcB = reinterpret_cast<const char*>(
            g_wU + ((size_t)comp * 512 + n0 + rowB) * 256 + q * 64);
        #pragma unroll
        for (int i = 0; i < 4; ++i) {
            const int kg = kgB0 + i;
            CP_ASYNC16(Bb + (uint32_t)rowB * 128 + (((uint32_t)kg ^ swB) << 4),
                       srcB + kg * 16, 16);
        }
    };

    load_chunk(0, 0); CP_COMMIT();
    load_chunk(1, 1); CP_COMMIT();

    const int qrow = l >> 2, qcol = (l & 3) * 2;

    #pragma unroll 1
    for (int qq = 0; qq < GW_NQQ; ++qq) {
        if (qq + 1 < GW_NQQ) CP_WAIT1(); else CP_WAIT0();
        __syncthreads();
        if (qq + 2 < GW_NQQ) { load_chunk(qq + 2, (qq + 2) % 3); CP_COMMIT(); }

        const uint32_t Ab = sb + GW_A(qq % 3), Bb = sb + GW_B(qq % 3);
        #pragma unroll
        for (int ks = 0; ks < 4; ++ks) {
            const uint32_t col = (((uint32_t)(ks * 2 + hi)) ^ swL) << 4;
            uint32_t af[4][4], bf[2][4];
            #pragma unroll
            for (int mt = 0; mt < 4; ++mt) ldm4(af[mt], Ab + aRow[mt] + col);
            #pragma unroll
            for (int nt = 0; nt < 2; ++nt) ldm4(bf[nt], Bb + bRow[nt] + col);
            #pragma unroll
            for (int mt = 0; mt < 4; ++mt)
                #pragma unroll
                for (int n8 = 0; n8 < 4; ++n8)
                    mma16816(acc[mt][n8], af[mt], bf[n8 >> 1][n8 & 1], bf[n8 >> 1][(n8 & 1) + 2]);
        }

        if ((qq & 3) == 3) {
            const int comp = c0 + (qq >> 2);
            #pragma unroll
            for (int mt = 0; mt < 4; ++mt) {
                #pragma unroll
                for (int n8 = 0; n8 < 4; ++n8) {
                    const int ch = wn + n8 * 8 + qcol;
                    #pragma unroll
                    for (int hlf = 0; hlf < 2; ++hlf) {
                        const int m = wm + mt * 16 + qrow + hlf * 8;
                        *reinterpret_cast<__half2*>(
                            g_M + ((size_t)(t0 + m) * 16 + comp) * 512 + n0 + ch) =
                            __floats2half2_rn(acc[mt][n8][2 * hlf], acc[mt][n8][2 * hlf + 1]);
                        acc[mt][n8][2 * hlf] = 0.0f;
                        acc[mt][n8][2 * hlf + 1] = 0.0f;
                    }
                }
            }
        }
    }
}

// ============================================================================
// Kernel 5 (FUSED): output transform + head GEMM + softmax + writes.
// 2 CTAs/SM; g_M reads are now tile-local (16KB contiguous per tile).
// ============================================================================
#define FH_AB      0u
#define FH_B(buf)  (16384u + (buf) * 16384u)
#define FH_CBIAS   49152u
#define FH_HBIAS   51200u
#define FH_SMEM    51712
#define FH_NCH     8

__global__ void __launch_bounds__(256, 2) headfuse_kernel(const float* __restrict__ bs,
                                                          const float* __restrict__ bc,
                                                          const float* __restrict__ br,
                                                          float* __restrict__ out)
{
    extern __shared__ char sm[];
    const uint32_t sb = smem_u32(sm);
    const int tid = threadIdx.x;
    const int t0 = blockIdx.x * 32;

    float* cb = reinterpret_cast<float*>(sm + FH_CBIAS);   // conv bias [512]
    float* hb = reinterpret_cast<float*>(sm + FH_HBIAS);   // head bias [128]
    #pragma unroll
    for (int i = 0; i < 2; ++i) cb[tid + 256 * i] = bs[tid + 256 * i];
    if (tid < 128)
        hb[tid] = (tid < 30) ? bc[tid] : (tid < 90 ? br[tid - 30] : 0.0f);

    const int rowB = tid >> 1;
    const int kgB0 = (tid & 1) * 4;
    const uint32_t swB = (uint32_t)(rowB & 7);

    const int w = tid >> 5, l = tid & 31;
    const int wm = (w >> 2) * 64, wn = (w & 3) * 24;
    const int lrow = l & 15, hi = l >> 4;
    const uint32_t swL = (uint32_t)(lrow & 7);
    uint32_t aRow[4], bRow[2];
    #pragma unroll
    for (int mt = 0; mt < 4; ++mt) aRow[mt] = (uint32_t)((wm + mt * 16 + lrow) * 128);
    #pragma unroll
    for (int nt = 0; nt < 2; ++nt) bRow[nt] = (uint32_t)((wn + nt * 16 + lrow) * 128);

    float acc[4][3][4];
    #pragma unroll
    for (int mt = 0; mt < 4; ++mt)
        #pragma unroll
        for (int n8 = 0; n8 < 3; ++n8)
            #pragma unroll
            for (int e = 0; e < 4; ++e) acc[mt][n8][e] = 0.0f;

    auto load_B = [&](int q, int buf) {
        const uint32_t Bb = sb + FH_B(buf);
        const char* srcB = reinterpret_cast<const char*>(
            g_wh + (size_t)rowB * 512 + q * 64);
        #pragma unroll
        for (int i = 0; i < 4; ++i) {
            const int kg = kgB0 + i;
            CP_ASYNC16(Bb + (uint32_t)rowB * 128 + (((uint32_t)kg ^ swB) << 4),
                       srcB + kg * 16, 16);
        }
    };

    auto produce_A = [&](int q) {
        #pragma unroll
        for (int it = 0; it < 4; ++it) {
            const int item = tid + 256 * it;
            const int tl = item >> 5;            // 0..31
            const int c2 = item & 31;            // ch pair within chunk
            const int t = t0 + tl;
            const int ch = q * 64 + 2 * c2;
            const __half* Mp = g_M + (size_t)t * 16 * 512 + ch;

            float2 m[4][4];
            #pragma unroll
            for (int i = 0; i < 4; ++i)
                #pragma unroll
                for (int j = 0; j < 4; ++j)
                    m[i][j] = __half22float2(*reinterpret_cast<const __half2*>(
                        Mp + (size_t)(i * 4 + j) * 512));

            float2 s[2][4];
            #pragma unroll
            for (int j = 0; j < 4; ++j) {
                s[0][j] = make_float2(m[0][j].x + m[1][j].x + m[2][j].x,
                                      m[0][j].y + m[1][j].y + m[2][j].y);
                s[1][j] = make_float2(m[1][j].x - m[2][j].x - m[3][j].x,
                                      m[1][j].y - m[2][j].y - m[3][j].y);
            }
            const float b0 = cb[ch], b1 = cb[ch + 1];
            const uint32_t grp = (uint32_t)(c2 >> 2);
            #pragma unroll
            for (int dy = 0; dy < 2; ++dy) {
                float2 y0 = make_float2(s[dy][0].x + s[dy][1].x + s[dy][2].x,
                                        s[dy][0].y + s[dy][1].y + s[dy][2].y);
                float2 y1 = make_float2(s[dy][1].x - s[dy][2].x - s[dy][3].x,
                                        s[dy][1].y - s[dy][2].y - s[dy][3].y);
                #pragma unroll
                for (int dx = 0; dx < 2; ++dx) {
                    const float2 yv = dx ? y1 : y0;
                    const float v0 = fminf(fmaxf(yv.x + b0, 0.0f), 6.0f);
                    const float v1 = fminf(fmaxf(yv.y + b1, 0.0f), 6.0f);
                    const int r = tl * 4 + dy * 2 + dx;
                    const uint32_t off = (uint32_t)r * 128 +
                        (grp ^ (uint32_t)(r & 7)) * 16 + ((uint32_t)c2 & 3) * 4;
                    *reinterpret_cast<__half2*>(sm + FH_AB + off) =
                        __floats2half2_rn(v0, v1);
                }
            }
        }
    };

    load_B(0, 0); CP_COMMIT();

    #pragma unroll 1
    for (int q = 0; q < FH_NCH; ++q) {
        produce_A(q);
        if (q + 1 < FH_NCH) { load_B(q + 1, (q + 1) & 1); CP_COMMIT(); CP_WAIT1(); }
        else CP_WAIT0();
        __syncthreads();

        const uint32_t Ab = sb + FH_AB, Bb = sb + FH_B(q & 1);
        #pragma unroll
        for (int ks = 0; ks < 4; ++ks) {
            const uint32_t col = (((uint32_t)(ks * 2 + hi)) ^ swL) << 4;
            uint32_t af[4][4], bf[2][4];
            #pragma unroll
            for (int mt = 0; mt < 4; ++mt) ldm4(af[mt], Ab + aRow[mt] + col);
            #pragma unroll
            for (int nt = 0; nt < 2; ++nt) ldm4(bf[nt], Bb + bRow[nt] + col);
            #pragma unroll
            for (int mt = 0; mt < 4; ++mt)
                #pragma unroll
                for (int n8 = 0; n8 < 3; ++n8)
                    mma16816(acc[mt][n8], af[mt], bf[n8 >> 1][n8 & 1], bf[n8 >> 1][(n8 & 1) + 2]);
        }
        __syncthreads();
    }

    const int qrow = l >> 2, qcol = (l & 3) * 2;
    #pragma unroll
    for (int mt = 0; mt < 4; ++mt) {
        #pragma unroll
        for (int n8 = 0; n8 < 3; ++n8) {
            const int ch = wn + n8 * 8 + qcol;
            if (ch >= 90) continue;
            const float b0 = hb[ch], b1 = hb[ch + 1];
            #pragma unroll
            for (int hlf = 0; hlf < 2; ++hlf) {
                const int m = wm + mt * 16 + qrow + hlf * 8;
                const int tl = m >> 2, dy = (m >> 1) & 1, dx = m & 1;
                const int t = t0 + tl;
                const size_t pos =
                    ((size_t)((t >> 12) * 128 + 2 * ((t >> 6) & 63) + dy)) * 128
                    + 2 * (t & 63) + dx;
                const float v0 = acc[mt][n8][2 * hlf]     + b0;
                const float v1 = acc[mt][n8][2 * hlf + 1] + b1;
                if (ch < 30) {
                    *reinterpret_cast<float2*>(out + pos * 30 + ch) = make_float2(v0, v1);
                    const float mx = fmaxf(v0, v1);
                    const float e0 = __expf(v0 - mx), e1 = __expf(v1 - mx);
                    const float inv = 1.0f / (e0 + e1);
                    *reinterpret_cast<float2*>(out + OFF_PROBS + pos * 30 + ch) =
                        make_float2(e0 * inv, e1 * inv);
                } else {
                    *reinterpret_cast<float2*>(out + OFF_DELTAS + pos * 60 + (ch - 30)) =
                        make_float2(v0, v1);
                }
            }
        }
    }
}

// ============================================================================
// Launch
// ============================================================================
extern "C" void kernel_launch(void* const* d_in, const int* in_sizes, int n_in,
                              void* d_out, int out_size) {
    const float* x  = (const float*)d_in[0];
    const float* ws = (const float*)d_in[1];
    const float* bs = (const float*)d_in[2];
    const float* wc = (const float*)d_in[3];
    const float* bc = (const float*)d_in[4];
    const float* wr = (const float*)d_in[5];
    const float* br = (const float*)d_in[6];
    float* out = (float*)d_out;

    cudaFuncSetAttribute(wino_gemm_kernel, cudaFuncAttributeMaxDynamicSharedMemorySize, GW_SMEM);
    cudaFuncSetAttribute(headfuse_kernel, cudaFuncAttributeMaxDynamicSharedMemorySize, FH_SMEM);

    wino_in_kernel<<<4096, 128>>>(x);
    wino_w_kernel<<<512, 256>>>(ws);
    cvt_wh_kernel<<<128, 512>>>(wc, wr);
    wino_gemm_kernel<<<1024, 512, GW_SMEM>>>();
    headfuse_kernel<<<1024, 256, FH_SMEM>>>(bs, bc, br, out);
}

// round 17
// speedup vs baseline: 1.0297x; 1.0050x over previous
#include <cuda_runtime.h>
#include <cuda_fp16.h>
#include <cstdint>

// ============================================================================
// RPNHead via Winograd F(2x2,3x3). R17 = R16 with:
//  - wino_in reworked to a 2x8 tile patch per block (6-row register window,
//    25% fewer x reads), and
//  - wino_in + wino_w + cvt_wh merged into ONE prep kernel (3072 blocks).
// GEMM and fused head kernels unchanged (proven).
// ============================================================================
#define NPOS 131072
#define NTIL 32768
#define OFF_PROBS  3932160
#define OFF_DELTAS 7864320

__device__ __align__(1024) __half g_V [(size_t)16*NTIL*256];   // input transform
__device__ __align__(1024) __half g_wU[(size_t)16*512*256];    // weight transform
__device__ __align__(1024) __half g_M [(size_t)NTIL*16*512];   // [tile][comp][ch]
__device__ __align__(1024) __half g_wh[(size_t)128*512];       // head W [j][c]

__device__ __forceinline__ uint32_t smem_u32(const void* p) {
    uint32_t a;
    asm("{ .reg .u64 t; cvta.to.shared.u64 t, %1; cvt.u32.u64 %0, t; }"
        : "=r"(a) : "l"(p));
    return a;
}

#define CP_ASYNC16(dst, src, sz) \
    asm volatile("cp.async.cg.shared.global [%0], [%1], 16, %2;" \
        :: "r"((uint32_t)(dst)), "l"(src), "r"((int)(sz)) : "memory")
#define CP_COMMIT() asm volatile("cp.async.commit_group;" ::: "memory")
#define CP_WAIT1()  asm volatile("cp.async.wait_group 1;" ::: "memory")
#define CP_WAIT0()  asm volatile("cp.async.wait_group 0;" ::: "memory")

__device__ __forceinline__ void ldm4(uint32_t* f, uint32_t addr) {
    asm volatile("ldmatrix.sync.aligned.m8n8.x4.shared.b16 {%0,%1,%2,%3}, [%4];"
        : "=r"(f[0]), "=r"(f[1]), "=r"(f[2]), "=r"(f[3]) : "r"(addr));
}
__device__ __forceinline__ void mma16816(float* c, const uint32_t* a,
                                         uint32_t b0, uint32_t b1) {
    asm volatile("mma.sync.aligned.m16n8k16.row.col.f32.f16.f16.f32 "
        "{%0,%1,%2,%3}, {%4,%5,%6,%7}, {%8,%9}, {%0,%1,%2,%3};"
        : "+f"(c[0]), "+f"(c[1]), "+f"(c[2]), "+f"(c[3])
        : "r"(a[0]), "r"(a[1]), "r"(a[2]), "r"(a[3]), "r"(b0), "r"(b1));
}

// ============================================================================
// Kernel 1 (MERGED PREP), 128 threads:
//  blk <  2048          : input transform, 2x8 tile patch, 6-row window
//  2048 <= blk < 2560   : weight transform (n = blk-2048, c = tid, tid+128)
//  2560 <= blk < 3072   : head weight pack
// ============================================================================
__global__ void __launch_bounds__(128) prep_kernel(const float* __restrict__ x,
                                                   const float* __restrict__ ws,
                                                   const float* __restrict__ wc,
                                                   const float* __restrict__ wr)
{
    const int blk = blockIdx.x;
    const int tid = threadIdx.x;

    if (blk < 2048) {
        // ---- input transform: 2 tile rows x 8 tile cols per block ----
        const int wgrp = blk & 7;
        const int thp  = (blk >> 3) & 31;     // tile-row pair
        const int b    = blk >> 8;
        const int c2   = tid;                 // channel pair
        const int tw0  = wgrp * 8;
        const int th0  = thp * 2;
        const int h0   = th0 * 2 - 1;         // rows h0 .. h0+5
        const int wbase = tw0 * 2 - 1;

        bool hv[6];
        const float* rowp[6];
        #pragma unroll
        for (int i = 0; i < 6; ++i) {
            const int h = h0 + i;
            hv[i] = (h >= 0) && (h < 128);
            rowp[i] = x + ((size_t)((b * 128 + (hv[i] ? h : 0)) * 128)) * 256 + 2 * c2;
        }
        auto ldcol = [&](int i, int wcn) -> float2 {
            if (hv[i] && wcn >= 0 && wcn < 128)
                return *reinterpret_cast<const float2*>(rowp[i] + (size_t)wcn * 256);
            return make_float2(0.0f, 0.0f);
        };

        float2 d[6][4];
        #pragma unroll
        for (int i = 0; i < 6; ++i)
            #pragma unroll
            for (int j = 0; j < 4; ++j)
                d[i][j] = ldcol(i, wbase + j);

        #pragma unroll 1
        for (int k = 0; k < 8; ++k) {
            #pragma unroll
            for (int r = 0; r < 2; ++r) {
                const int t = (b * 64 + th0 + r) * 64 + (tw0 + k);
                float2 tr[4][4];
                #pragma unroll
                for (int j = 0; j < 4; ++j) {
                    const float2 d0 = d[2*r+0][j], d1 = d[2*r+1][j],
                                 d2 = d[2*r+2][j], d3 = d[2*r+3][j];
                    tr[0][j] = make_float2(d0.x - d2.x, d0.y - d2.y);
                    tr[1][j] = make_float2(d1.x + d2.x, d1.y + d2.y);
                    tr[2][j] = make_float2(d2.x - d1.x, d2.y - d1.y);
                    tr[3][j] = make_float2(d1.x - d3.x, d1.y - d3.y);
                }
                #pragma unroll
                for (int i = 0; i < 4; ++i) {
                    float2 v0 = make_float2(tr[i][0].x - tr[i][2].x, tr[i][0].y - tr[i][2].y);
                    float2 v1 = make_float2(tr[i][1].x + tr[i][2].x, tr[i][1].y + tr[i][2].y);
                    float2 v2 = make_float2(tr[i][2].x - tr[i][1].x, tr[i][2].y - tr[i][1].y);
                    float2 v3 = make_float2(tr[i][1].x - tr[i][3].x, tr[i][1].y - tr[i][3].y);
                    *reinterpret_cast<__half2*>(g_V + ((size_t)(i*4+0)*NTIL + t)*256 + 2*c2) = __floats2half2_rn(v0.x, v0.y);
                    *reinterpret_cast<__half2*>(g_V + ((size_t)(i*4+1)*NTIL + t)*256 + 2*c2) = __floats2half2_rn(v1.x, v1.y);
                    *reinterpret_cast<__half2*>(g_V + ((size_t)(i*4+2)*NTIL + t)*256 + 2*c2) = __floats2half2_rn(v2.x, v2.y);
                    *reinterpret_cast<__half2*>(g_V + ((size_t)(i*4+3)*NTIL + t)*256 + 2*c2) = __floats2half2_rn(v3.x, v3.y);
                }
            }
            if (k < 7) {
                #pragma unroll
                for (int i = 0; i < 6; ++i) {
                    d[i][0] = d[i][2];
                    d[i][1] = d[i][3];
                    d[i][2] = ldcol(i, wbase + 2 * k + 4);
                    d[i][3] = ldcol(i, wbase + 2 * k + 5);
                }
            }
        }
    } else if (blk < 2560) {
        // ---- weight transform U = G g Gt ----
        const int n = blk - 2048;
        #pragma unroll
        for (int cc = 0; cc < 2; ++cc) {
            const int c = tid + cc * 128;
            float g[3][3];
            #pragma unroll
            for (int kh = 0; kh < 3; ++kh)
                #pragma unroll
                for (int kw = 0; kw < 3; ++kw)
                    g[kh][kw] = ws[((size_t)(kh * 3 + kw) * 256 + c) * 512 + n];
            float u[4][3];
            #pragma unroll
            for (int kw = 0; kw < 3; ++kw) {
                u[0][kw] = g[0][kw];
                u[1][kw] = 0.5f * (g[0][kw] + g[1][kw] + g[2][kw]);
                u[2][kw] = 0.5f * (g[0][kw] - g[1][kw] + g[2][kw]);
                u[3][kw] = g[2][kw];
            }
            #pragma unroll
            for (int r = 0; r < 4; ++r) {
                float U0 = u[r][0];
                float U1 = 0.5f * (u[r][0] + u[r][1] + u[r][2]);
                float U2 = 0.5f * (u[r][0] - u[r][1] + u[r][2]);
                float U3 = u[r][2];
                g_wU[((size_t)(r * 4 + 0) * 512 + n) * 256 + c] = __float2half(U0);
                g_wU[((size_t)(r * 4 + 1) * 512 + n) * 256 + c] = __float2half(U1);
                g_wU[((size_t)(r * 4 + 2) * 512 + n) * 256 + c] = __float2half(U2);
                g_wU[((size_t)(r * 4 + 3) * 512 + n) * 256 + c] = __float2half(U3);
            }
        }
    } else {
        // ---- head weight pack ----
        const int idx = (blk - 2560) * 128 + tid;   // 0..65535
        const int j = idx >> 9, c = idx & 511;
        float v = 0.0f;
        if (j < 30)      v = wc[c * 30 + j];
        else if (j < 90) v = wr[c * 60 + (j - 30)];
        g_wh[(size_t)j * 512 + c] = __float2half(v);
    }
}

// ============================================================================
// Kernel 2: persistent batched GEMM (proven 3-stage, 1 barrier/chunk).
// Epilogue writes g_M in [tile][comp][ch] layout.
// ============================================================================
#define GW_STG     49152u
#define GW_A(s)    ((s) * GW_STG)
#define GW_B(s)    ((s) * GW_STG + 16384u)
#define GW_SMEM    147456
#define GW_NQQ     32

__global__ void __launch_bounds__(512, 1) wino_gemm_kernel()
{
    extern __shared__ char sm[];
    const uint32_t sb = smem_u32(sm);
    const int tid = threadIdx.x;
    const int mblk = blockIdx.x >> 2;
    const int n0 = ((blockIdx.x >> 1) & 1) << 8;
    const int c0 = (blockIdx.x & 1) << 3;
    const int t0 = mblk << 7;

    const int rowA = tid >> 2;
    const int kgA0 = (tid * 2) & 7;
    const int rowB = tid >> 1;
    const int kgB0 = (tid * 4) & 7;
    const uint32_t swA = (uint32_t)(rowA & 7);
    const uint32_t swB = (uint32_t)(rowB & 7);

    const int w = tid >> 5, l = tid & 31;
    const int wm = (w >> 3) * 64, wn = (w & 7) * 32;
    const int lrow = l & 15, hi = l >> 4;
    const uint32_t swL = (uint32_t)(lrow & 7);
    uint32_t aRow[4], bRow[2];
    #pragma unroll
    for (int mt = 0; mt < 4; ++mt) aRow[mt] = (uint32_t)((wm + mt * 16 + lrow) * 128);
    #pragma unroll
    for (int nt = 0; nt < 2; ++nt) bRow[nt] = (uint32_t)((wn + nt * 16 + lrow) * 128);

    float acc[4][4][4];
    #pragma unroll
    for (int mt = 0; mt < 4; ++mt)
        #pragma unroll
        for (int n8 = 0; n8 < 4; ++n8)
            #pragma unroll
            for (int e = 0; e < 4; ++e) acc[mt][n8][e] = 0.0f;

    auto load_chunk = [&](int qq, int s) {
        const int comp = c0 + (qq >> 2), q = qq & 3;
        const uint32_t Ab = sb + GW_A(s), Bb = sb + GW_B(s);
        const char* srcA = reinterpret_cast<const char*>(
            g_V + ((size_t)comp * NTIL + t0 + rowA) * 256 + q * 64);
        #pragma unroll
        for (int i = 0; i < 2; ++i) {
            const int kg = kgA0 + i;
            CP_ASYNC16(Ab + (uint32_t)rowA * 128 + (((uint32_t)kg ^ swA) << 4),
                       srcA + kg * 16, 16);
        }
        const char* srcB = reinterpret_cast<const char*>(
            g_wU + ((size_t)comp * 512 + n0 + rowB) * 256 + q * 64);
        #pragma unroll
        for (int i = 0; i < 4; ++i) {
            const int kg = kgB0 + i;
            CP_ASYNC16(Bb + (uint32_t)rowB * 128 + (((uint32_t)kg ^ swB) << 4),
                       srcB + kg * 16, 16);
        }
    };

    load_chunk(0, 0); CP_COMMIT();
    load_chunk(1, 1); CP_COMMIT();

    const int qrow = l >> 2, qcol = (l & 3) * 2;

    #pragma unroll 1
    for (int qq = 0; qq < GW_NQQ; ++qq) {
        if (qq + 1 < GW_NQQ) CP_WAIT1(); else CP_WAIT0();
        __syncthreads();
        if (qq + 2 < GW_NQQ) { load_chunk(qq + 2, (qq + 2) % 3); CP_COMMIT(); }

        const uint32_t Ab = sb + GW_A(qq % 3), Bb = sb + GW_B(qq % 3);
        #pragma unroll
        for (int ks = 0; ks < 4; ++ks) {
            const uint32_t col = (((uint32_t)(ks * 2 + hi)) ^ swL) << 4;
            uint32_t af[4][4], bf[2][4];
            #pragma unroll
            for (int mt = 0; mt < 4; ++mt) ldm4(af[mt], Ab + aRow[mt] + col);
            #pragma unroll
            for (int nt = 0; nt < 2; ++nt) ldm4(bf[nt], Bb + bRow[nt] + col);
            #pragma unroll
            for (int mt = 0; mt < 4; ++mt)
                #pragma unroll
                for (int n8 = 0; n8 < 4; ++n8)
                    mma16816(acc[mt][n8], af[mt], bf[n8 >> 1][n8 & 1], bf[n8 >> 1][(n8 & 1) + 2]);
        }

        if ((qq & 3) == 3) {
            const int comp = c0 + (qq >> 2);
            #pragma unroll
            for (int mt = 0; mt < 4; ++mt) {
                #pragma unroll
                for (int n8 = 0; n8 < 4; ++n8) {
                    const int ch = wn + n8 * 8 + qcol;
                    #pragma unroll
                    for (int hlf = 0; hlf < 2; ++hlf) {
                        const int m = wm + mt * 16 + qrow + hlf * 8;
                        *reinterpret_cast<__half2*>(
                            g_M + ((size_t)(t0 + m) * 16 + comp) * 512 + n0 + ch) =
                            __floats2half2_rn(acc[mt][n8][2 * hlf], acc[mt][n8][2 * hlf + 1]);
                        acc[mt][n8][2 * hlf] = 0.0f;
                        acc[mt][n8][2 * hlf + 1] = 0.0f;
                    }
                }
            }
        }
    }
}

// ============================================================================
// Kernel 3 (FUSED): output transform + head GEMM + softmax + writes.
// 2 CTAs/SM; g_M reads are tile-local (16KB contiguous per tile).
// ============================================================================
#define FH_AB      0u
#define FH_B(buf)  (16384u + (buf) * 16384u)
#define FH_CBIAS   49152u
#define FH_HBIAS   51200u
#define FH_SMEM    51712
#define FH_NCH     8

__global__ void __launch_bounds__(256, 2) headfuse_kernel(const float* __restrict__ bs,
                                                          const float* __restrict__ bc,
                                                          const float* __restrict__ br,
                                                          float* __restrict__ out)
{
    extern __shared__ char sm[];
    const uint32_t sb = smem_u32(sm);
    const int tid = threadIdx.x;
    const int t0 = blockIdx.x * 32;

    float* cb = reinterpret_cast<float*>(sm + FH_CBIAS);   // conv bias [512]
    float* hb = reinterpret_cast<float*>(sm + FH_HBIAS);   // head bias [128]
    #pragma unroll
    for (int i = 0; i < 2; ++i) cb[tid + 256 * i] = bs[tid + 256 * i];
    if (tid < 128)
        hb[tid] = (tid < 30) ? bc[tid] : (tid < 90 ? br[tid - 30] : 0.0f);

    const int rowB = tid >> 1;
    const int kgB0 = (tid & 1) * 4;
    const uint32_t swB = (uint32_t)(rowB & 7);

    const int w = tid >> 5, l = tid & 31;
    const int wm = (w >> 2) * 64, wn = (w & 3) * 24;
    const int lrow = l & 15, hi = l >> 4;
    const uint32_t swL = (uint32_t)(lrow & 7);
    uint32_t aRow[4], bRow[2];
    #pragma unroll
    for (int mt = 0; mt < 4; ++mt) aRow[mt] = (uint32_t)((wm + mt * 16 + lrow) * 128);
    #pragma unroll
    for (int nt = 0; nt < 2; ++nt) bRow[nt] = (uint32_t)((wn + nt * 16 + lrow) * 128);

    float acc[4][3][4];
    #pragma unroll
    for (int mt = 0; mt < 4; ++mt)
        #pragma unroll
        for (int n8 = 0; n8 < 3; ++n8)
            #pragma unroll
            for (int e = 0; e < 4; ++e) acc[mt][n8][e] = 0.0f;

    auto load_B = [&](int q, int buf) {
        const uint32_t Bb = sb + FH_B(buf);
        const char* srcB = reinterpret_cast<const char*>(
            g_wh + (size_t)rowB * 512 + q * 64);
        #pragma unroll
        for (int i = 0; i < 4; ++i) {
            const int kg = kgB0 + i;
            CP_ASYNC16(Bb + (uint32_t)rowB * 128 + (((uint32_t)kg ^ swB) << 4),
                       srcB + kg * 16, 16);
        }
    };

    auto produce_A = [&](int q) {
        #pragma unroll
        for (int it = 0; it < 4; ++it) {
            const int item = tid + 256 * it;
            const int tl = item >> 5;            // 0..31
            const int c2 = item & 31;            // ch pair within chunk
            const int t = t0 + tl;
            const int ch = q * 64 + 2 * c2;
            const __half* Mp = g_M + (size_t)t * 16 * 512 + ch;

            float2 m[4][4];
            #pragma unroll
            for (int i = 0; i < 4; ++i)
                #pragma unroll
                for (int j = 0; j < 4; ++j)
                    m[i][j] = __half22float2(*reinterpret_cast<const __half2*>(
                        Mp + (size_t)(i * 4 + j) * 512));

            float2 s[2][4];
            #pragma unroll
            for (int j = 0; j < 4; ++j) {
                s[0][j] = make_float2(m[0][j].x + m[1][j].x + m[2][j].x,
                                      m[0][j].y + m[1][j].y + m[2][j].y);
                s[1][j] = make_float2(m[1][j].x - m[2][j].x - m[3][j].x,
                                      m[1][j].y - m[2][j].y - m[3][j].y);
            }
            const float b0 = cb[ch], b1 = cb[ch + 1];
            const uint32_t grp = (uint32_t)(c2 >> 2);
            #pragma unroll
            for (int dy = 0; dy < 2; ++dy) {
                float2 y0 = make_float2(s[dy][0].x + s[dy][1].x + s[dy][2].x,
                                        s[dy][0].y + s[dy][1].y + s[dy][2].y);
                float2 y1 = make_float2(s[dy][1].x - s[dy][2].x - s[dy][3].x,
                                        s[dy][1].y - s[dy][2].y - s[dy][3].y);
                #pragma unroll
                for (int dx = 0; dx < 2; ++dx) {
                    const float2 yv = dx ? y1 : y0;
                    const float v0 = fminf(fmaxf(yv.x + b0, 0.0f), 6.0f);
                    const float v1 = fminf(fmaxf(yv.y + b1, 0.0f), 6.0f);
                    const int r = tl * 4 + dy * 2 + dx;
                    const uint32_t off = (uint32_t)r * 128 +
                        (grp ^ (uint32_t)(r & 7)) * 16 + ((uint32_t)c2 & 3) * 4;
                    *reinterpret_cast<__half2*>(sm + FH_AB + off) =
                        __floats2half2_rn(v0, v1);
                }
            }
        }
    };

    load_B(0, 0); CP_COMMIT();

    #pragma unroll 1
    for (int q = 0; q < FH_NCH; ++q) {
        produce_A(q);
        if (q + 1 < FH_NCH) { load_B(q + 1, (q + 1) & 1); CP_COMMIT(); CP_WAIT1(); }
        else CP_WAIT0();
        __syncthreads();

        const uint32_t Ab = sb + FH_AB, Bb = sb + FH_B(q & 1);
        #pragma unroll
        for (int ks = 0; ks < 4; ++ks) {
            const uint32_t col = (((uint32_t)(ks * 2 + hi)) ^ swL) << 4;
            uint32_t af[4][4], bf[2][4];
            #pragma unroll
            for (int mt = 0; mt < 4; ++mt) ldm4(af[mt], Ab + aRow[mt] + col);
            #pragma unroll
            for (int nt = 0; nt < 2; ++nt) ldm4(bf[nt], Bb + bRow[nt] + col);
            #pragma unroll
            for (int mt = 0; mt < 4; ++mt)
                #pragma unroll
                for (int n8 = 0; n8 < 3; ++n8)
                    mma16816(acc[mt][n8], af[mt], bf[n8 >> 1][n8 & 1], bf[n8 >> 1][(n8 & 1) + 2]);
        }
        __syncthreads();
    }

    const int qrow = l >> 2, qcol = (l & 3) * 2;
    #pragma unroll
    for (int mt = 0; mt < 4; ++mt) {
        #pragma unroll
        for (int n8 = 0; n8 < 3; ++n8) {
            const int ch = wn + n8 * 8 + qcol;
            if (ch >= 90) continue;
            const float b0 = hb[ch], b1 = hb[ch + 1];
            #pragma unroll
            for (int hlf = 0; hlf < 2; ++hlf) {
                const int m = wm + mt * 16 + qrow + hlf * 8;
                const int tl = m >> 2, dy = (m >> 1) & 1, dx = m & 1;
                const int t = t0 + tl;
                const size_t pos =
                    ((size_t)((t >> 12) * 128 + 2 * ((t >> 6) & 63) + dy)) * 128
                    + 2 * (t & 63) + dx;
                const float v0 = acc[mt][n8][2 * hlf]     + b0;
                const float v1 = acc[mt][n8][2 * hlf + 1] + b1;
                if (ch < 30) {
                    *reinterpret_cast<float2*>(out + pos * 30 + ch) = make_float2(v0, v1);
                    const float mx = fmaxf(v0, v1);
                    const float e0 = __expf(v0 - mx), e1 = __expf(v1 - mx);
                    const float inv = 1.0f / (e0 + e1);
                    *reinterpret_cast<float2*>(out + OFF_PROBS + pos * 30 + ch) =
                        make_float2(e0 * inv, e1 * inv);
                } else {
                    *reinterpret_cast<float2*>(out + OFF_DELTAS + pos * 60 + (ch - 30)) =
                        make_float2(v0, v1);
                }
            }
        }
    }
}

// ============================================================================
// Launch
// ============================================================================
extern "C" void kernel_launch(void* const* d_in, const int* in_sizes, int n_in,
                              void* d_out, int out_size) {
    const float* x  = (const float*)d_in[0];
    const float* ws = (const float*)d_in[1];
    const float* bs = (const float*)d_in[2];
    const float* wc = (const float*)d_in[3];
    const float* bc = (const float*)d_in[4];
    const float* wr = (const float*)d_in[5];
    const float* br = (const float*)d_in[6];
    float* out = (float*)d_out;

    cudaFuncSetAttribute(wino_gemm_kernel, cudaFuncAttributeMaxDynamicSharedMemorySize, GW_SMEM);
    cudaFuncSetAttribute(headfuse_kernel, cudaFuncAttributeMaxDynamicSharedMemorySize, FH_SMEM);

    prep_kernel<<<3072, 128>>>(x, ws, wc, wr);
    wino_gemm_kernel<<<1024, 512, GW_SMEM>>>();
    headfuse_kernel<<<1024, 256, FH_SMEM>>>(bs, bc, br, out);
}